// round 13
// baseline (speedup 1.0000x reference)
#include <cuda_runtime.h>
#include <cstdint>

#define DT    0.04f
#define DT2   (0.04f * 0.04f * 0.5f)
#define AXM   9.0f
#define PDM   1.244f
#define SPM   20.0f

#define BLK     128      // threads per block = trajectories per block
#define TCHUNK  8        // time steps per tile
#define NTILE   (128 / TCHUNK)          // 16
#define IN_F4   4                       // float4 motion / traj / tile
#define OUT_F4  8                       // float4 output / traj / tile

// XOR swizzles (replace padding; keep smem at 32 KiB for 7 CTAs/SM)
#define SW_IN(row, col)   ((col) ^ (((row) >> 1) & 3))   // s_in  [.][128][4]
#define SW_OUT(row, col)  ((col) ^ ((row) & 7))          // s_out [128][8]

__device__ __forceinline__ void cp_async16(void* smem_dst, const void* gmem_src) {
    uint32_t s = (uint32_t)__cvta_generic_to_shared(smem_dst);
    asm volatile("cp.async.cg.shared.global [%0], [%1], 16;\n" :: "r"(s), "l"(gmem_src));
}
__device__ __forceinline__ void cp_async_commit() {
    asm volatile("cp.async.commit_group;\n" ::: "memory");
}
__device__ __forceinline__ void cp_async_wait1() {
    asm volatile("cp.async.wait_group 1;\n" ::: "memory");
}

__device__ __forceinline__ void step(float& x, float& y, float& v, float& psi,
                                     float m0, float m1) {
    float ax = fminf(fmaxf(m0, -AXM), AXM);
    float pd = fminf(fmaxf(m1, -PDM), PDM);
    float sn, cs;
    __sincosf(psi, &sn, &cs);
    x = fmaf(v * cs, DT, fmaf(fmaf(ax, cs, -pd * v * sn), DT2, x));
    y = fmaf(v * sn, DT, fmaf(fmaf(ax, sn,  pd * v * cs), DT2, y));
    v = fminf(fmaxf(fmaf(ax, DT, v), -SPM), SPM);
    psi = fmaf(pd, DT, psi);
}

__global__ __launch_bounds__(BLK)      // no reg cap (R5 lesson)
void kin_kernel(const float4* __restrict__ motion,   // [B,128,2] = 64 f4/traj
                const float4* __restrict__ init,     // [B,4]
                float4* __restrict__ out)            // [B,128,4] = 128 f4/traj
{
    __shared__ float4 s_in [2][BLK][IN_F4];   // 16 KiB, double-buffered (cp.async dst)
    __shared__ float4 s_out[BLK][OUT_F4];     // 16 KiB

    const int tid = threadIdx.x;
    const int b0  = blockIdx.x * BLK;

    float4 s = init[b0 + tid];
    float x = s.x, y = s.y, v = s.z, psi = s.w;

    const int irow = tid >> 2, icol = tid & 3;    // staging: 4 lanes/traj
    const int orow = tid >> 3, ocol = tid & 7;    // drain:   8 lanes/traj
    const float4* mbase = motion + (size_t)b0 * 64;
    float4*       obase = out    + (size_t)b0 * 128;

    // prologue: fill stages 0 and 1 with tiles 0 and 1 (two cp.async groups)
    #pragma unroll
    for (int k = 0; k < IN_F4; k++) {
        int r = irow + k * 32;
        cp_async16(&s_in[0][r][SW_IN(r, icol)],
                   &mbase[(size_t)r * 64 + icol]);
    }
    cp_async_commit();
    #pragma unroll
    for (int k = 0; k < IN_F4; k++) {
        int r = irow + k * 32;
        cp_async16(&s_in[1][r][SW_IN(r, icol)],
                   &mbase[(size_t)r * 64 + IN_F4 + icol]);
    }
    cp_async_commit();

    #pragma unroll 1
    for (int tile = 0; tile < NTILE; tile++) {
        const int st = tile & 1;

        // fill(tile) complete (<=1 group may remain outstanding)
        cp_async_wait1();
        __syncthreads();

        // compute 8 steps from own smem row, stage results (swizzled)
        #pragma unroll
        for (int j = 0; j < IN_F4; j++) {
            float4 mp = s_in[st][tid][SW_IN(tid, j)];
            step(x, y, v, psi, mp.x, mp.y);
            s_out[tid][SW_OUT(tid, 2 * j)]     = make_float4(x, y, v, psi);
            step(x, y, v, psi, mp.z, mp.w);
            s_out[tid][SW_OUT(tid, 2 * j + 1)] = make_float4(x, y, v, psi);
        }
        __syncthreads();   // s_out ready; all reads of s_in[st] done

        // refill freed stage with tile+2 (always commit -> uniform group count)
        if (tile + 2 < NTILE) {
            #pragma unroll
            for (int k = 0; k < IN_F4; k++) {
                int r = irow + k * 32;
                cp_async16(&s_in[st][r][SW_IN(r, icol)],
                           &mbase[(size_t)r * 64 + (tile + 2) * IN_F4 + icol]);
            }
        }
        cp_async_commit();

        // drain: fully coalesced STG.128 (full 128B lines), streaming hint
        #pragma unroll
        for (int k = 0; k < OUT_F4; k++) {
            int r = orow + k * 16;
            __stcs(&obase[(size_t)r * 128 + tile * OUT_F4 + ocol],
                   s_out[r][SW_OUT(r, ocol)]);
        }
        __syncthreads();   // drain reads done before s_out rewritten
    }
}

extern "C" void kernel_launch(void* const* d_in, const int* in_sizes, int n_in,
                              void* d_out, int out_size) {
    const float4* motion = (const float4*)d_in[0];
    const float4* init   = (const float4*)d_in[1];
    float4*       out    = (float4*)d_out;

    int B = in_sizes[1] / 4;          // 262144
    int blocks = B / BLK;             // 2048
    kin_kernel<<<blocks, BLK>>>(motion, init, out);
}